// round 12
// baseline (speedup 1.0000x reference)
#include <cuda_runtime.h>
#include <cuda_bf16.h>
#include <cstdint>

#define B_  4
#define S_  2048
#define TD  768
#define HID 512
#define NH  8
#define HD  64
#define VD  768
#define M_  (B_*S_)   // 8192
#define TDHID (TD*HID)

// Scratch (allocation-free rule: __device__ globals) — all intermediates split bf16 hi/lo
__device__ __nv_bfloat16 g_xh[M_*TD],  g_xl[M_*TD];
__device__ __nv_bfloat16 g_qh[M_*HID], g_ql[M_*HID];
__device__ __nv_bfloat16 g_kh[M_*HID], g_kl[M_*HID];
__device__ __nv_bfloat16 g_vh[M_*HID], g_vl[M_*HID];
__device__ __nv_bfloat16 g_ath[M_*HID], g_atl[M_*HID];
// transposed + split weights: [0..3*TDHID) = Wq,Wk,Wv as [n][k]; [3*TDHID..) = Wo as [n][k]
__device__ __nv_bfloat16 g_bh[3*TDHID + VD*HID];
__device__ __nv_bfloat16 g_bl[3*TDHID + VD*HID];

struct alignas(8) bf4 { __nv_bfloat16 v[4]; };

__device__ __forceinline__ uint32_t smem_u32(const void* p) {
    uint32_t a;
    asm("{ .reg .u64 t; cvta.to.shared.u64 t, %1; cvt.u32.u64 %0, t; }" : "=r"(a) : "l"(p));
    return a;
}
__device__ __forceinline__ void splitf(float x, __nv_bfloat16& h, __nv_bfloat16& l) {
    h = __float2bfloat16(x);
    l = __float2bfloat16(x - __bfloat162float(h));
}
__device__ __forceinline__ uint32_t packraw(__nv_bfloat16 a, __nv_bfloat16 b) {
    return ((uint32_t)*(uint16_t*)&b << 16) | *(uint16_t*)&a;
}

// ============================ input prep: split X once ============================
__global__ __launch_bounds__(256) void prep_split(const float* __restrict__ X)
{
    const int idx = blockIdx.x * 256 + threadIdx.x;   // over float4
    float4 a = *(const float4*)&X[(size_t)idx * 4];
    bf4 h, l;
    splitf(a.x, h.v[0], l.v[0]); splitf(a.y, h.v[1], l.v[1]);
    splitf(a.z, h.v[2], l.v[2]); splitf(a.w, h.v[3], l.v[3]);
    *(bf4*)&g_xh[(size_t)idx * 4] = h;
    *(bf4*)&g_xl[(size_t)idx * 4] = l;
}

// ============================ weight prep: transpose + bf16 split ============================
__global__ __launch_bounds__(256) void prep_transpose(const float* __restrict__ W,
                                                      int rows, int cols, int dst_off)
{
    __shared__ float t[32][33];
    const int tx = threadIdx.x & 31, ty = threadIdx.x >> 5;
    const int k0 = blockIdx.x * 32, n0 = blockIdx.y * 32;
#pragma unroll
    for (int j = 0; j < 4; j++) {
        const int k = k0 + ty + j * 8;
        t[ty + j * 8][tx] = W[(size_t)k * cols + n0 + tx];
    }
    __syncthreads();
#pragma unroll
    for (int j = 0; j < 4; j++) {
        const int n = n0 + ty + j * 8;
        const int k = k0 + tx;
        const float x = t[tx][ty + j * 8];
        __nv_bfloat16 h, l; splitf(x, h, l);
        g_bh[dst_off + (size_t)n * rows + k] = h;
        g_bl[dst_off + (size_t)n * rows + k] = l;
    }
}

// ============================ mma.sync helpers ============================
__device__ __forceinline__ void mma16816(float* d, const uint32_t* a, const uint32_t* b)
{
    asm volatile(
        "mma.sync.aligned.m16n8k16.row.col.f32.bf16.bf16.f32 "
        "{%0,%1,%2,%3}, {%4,%5,%6,%7}, {%8,%9}, {%0,%1,%2,%3};"
        : "+f"(d[0]), "+f"(d[1]), "+f"(d[2]), "+f"(d[3])
        : "r"(a[0]), "r"(a[1]), "r"(a[2]), "r"(a[3]), "r"(b[0]), "r"(b[1]));
}
__device__ __forceinline__ void ldmx4t(uint32_t* r, uint32_t addr)
{
    asm volatile("ldmatrix.sync.aligned.m8n8.x4.trans.shared.b16 {%0,%1,%2,%3}, [%4];"
                 : "=r"(r[0]), "=r"(r[1]), "=r"(r[2]), "=r"(r[3]) : "r"(addr));
}
__device__ __forceinline__ void ldmx4n(uint32_t* r, uint32_t addr)
{
    asm volatile("ldmatrix.sync.aligned.m8n8.x4.shared.b16 {%0,%1,%2,%3}, [%4];"
                 : "=r"(r[0]), "=r"(r[1]), "=r"(r[2]), "=r"(r[3]) : "r"(addr));
}

// ============================ mma.sync split-bf16 GEMM (projections) ============================
// A pre-split bf16: outsel<3 -> g_xh/g_xl; outsel 3 -> g_ath/g_atl.
// outsel 0/1/2: head-major split bf16 into g_{q,k,v}{h,l} (Q pre-scaled by 0.125)
// outsel 3: fp32 row-major into outp.
#define APAD 40

__global__ __launch_bounds__(256) void mma_gemm(
    const float* __restrict__ bias, float* __restrict__ outp,
    int ktot, int ntot, int boff, int outsel)
{
    __shared__ __nv_bfloat16 sAh[128 * APAD];
    __shared__ __nv_bfloat16 sAl[128 * APAD];
    __shared__ __nv_bfloat16 sBh[128 * APAD];
    __shared__ __nv_bfloat16 sBl[128 * APAD];

    const int tid = threadIdx.x;
    const int wid = tid >> 5, lid = tid & 31;
    const int wm = wid >> 1, wn = wid & 1;
    const int g = lid >> 2, tg = lid & 3;
    const int rowBase = blockIdx.y * 128;
    const int colBase = blockIdx.x * 128;
    const int nc = ktot / 32;

    const __nv_bfloat16* Ah = (outsel == 3) ? g_ath : g_xh;
    const __nv_bfloat16* Al = (outsel == 3) ? g_atl : g_xl;
    const __nv_bfloat16* Bh = g_bh + boff;
    const __nv_bfloat16* Bl = g_bl + boff;

    float acc[2][8][4];
#pragma unroll
    for (int i = 0; i < 2; i++)
#pragma unroll
        for (int j = 0; j < 8; j++)
#pragma unroll
            for (int r = 0; r < 4; r++) acc[i][j][r] = 0.f;

    for (int c = 0; c < nc; c++) {
        // ---- A chunk: 128 rows x 32 k, pre-split copies ----
        {
            const __nv_bfloat16* Ah_src = Ah + (size_t)rowBase * ktot + c * 32;
            const __nv_bfloat16* Al_src = Al + (size_t)rowBase * ktot + c * 32;
#pragma unroll
            for (int it = 0; it < 2; it++) {
                const int idx = it * 256 + tid;       // 512 uint4
                const int n = idx >> 2, c8 = idx & 3;
                const size_t so = (size_t)n * ktot + c8 * 8;
                *(uint4*)&sAh[n * APAD + c8 * 8] = *(const uint4*)&Ah_src[so];
                *(uint4*)&sAl[n * APAD + c8 * 8] = *(const uint4*)&Al_src[so];
            }
        }
        // ---- B chunk: 128 n-rows x 32 k ----
        {
#pragma unroll
            for (int it = 0; it < 2; it++) {
                const int idx = it * 256 + tid;
                const int n = idx >> 2, c8 = idx & 3;
                const size_t go = (size_t)(colBase + n) * ktot + c * 32 + c8 * 8;
                *(uint4*)&sBh[n * APAD + c8 * 8] = *(const uint4*)&Bh[go];
                *(uint4*)&sBl[n * APAD + c8 * 8] = *(const uint4*)&Bl[go];
            }
        }
        __syncthreads();

#pragma unroll
        for (int ks = 0; ks < 2; ks++) {
            const int k0 = ks * 16 + tg * 2;
            uint32_t ah[2][4], al[2][4];
#pragma unroll
            for (int i = 0; i < 2; i++) {
                const int r0 = wm * 32 + i * 16 + g;
                ah[i][0] = *(const uint32_t*)&sAh[r0 * APAD + k0];
                ah[i][1] = *(const uint32_t*)&sAh[(r0 + 8) * APAD + k0];
                ah[i][2] = *(const uint32_t*)&sAh[r0 * APAD + k0 + 8];
                ah[i][3] = *(const uint32_t*)&sAh[(r0 + 8) * APAD + k0 + 8];
                al[i][0] = *(const uint32_t*)&sAl[r0 * APAD + k0];
                al[i][1] = *(const uint32_t*)&sAl[(r0 + 8) * APAD + k0];
                al[i][2] = *(const uint32_t*)&sAl[r0 * APAD + k0 + 8];
                al[i][3] = *(const uint32_t*)&sAl[(r0 + 8) * APAD + k0 + 8];
            }
#pragma unroll
            for (int j = 0; j < 8; j++) {
                const int n0 = wn * 64 + j * 8 + g;
                uint32_t bh[2], bl[2];
                bh[0] = *(const uint32_t*)&sBh[n0 * APAD + k0];
                bh[1] = *(const uint32_t*)&sBh[n0 * APAD + k0 + 8];
                bl[0] = *(const uint32_t*)&sBl[n0 * APAD + k0];
                bl[1] = *(const uint32_t*)&sBl[n0 * APAD + k0 + 8];
#pragma unroll
                for (int i = 0; i < 2; i++) {
                    mma16816(acc[i][j], ah[i], bh);
                    mma16816(acc[i][j], ah[i], bl);
                    mma16816(acc[i][j], al[i], bh);
                }
            }
        }
        __syncthreads();
    }

    // ---- epilogue ----
    __nv_bfloat16* oh = (outsel == 0) ? g_qh : (outsel == 1) ? g_kh : g_vh;
    __nv_bfloat16* ol = (outsel == 0) ? g_ql : (outsel == 1) ? g_kl : g_vl;
    const float sc = (outsel == 0) ? 0.125f : 1.f;    // fold 1/sqrt(64) into Q
#pragma unroll
    for (int i = 0; i < 2; i++) {
        const int m0 = rowBase + wm * 32 + i * 16 + g;
#pragma unroll
        for (int j = 0; j < 8; j++) {
            const int n = colBase + wn * 64 + j * 8 + tg * 2;
            const float bx = __ldg(&bias[n]), by = __ldg(&bias[n + 1]);
            if (outsel < 3) {
                const float a0 = (acc[i][j][0] + bx) * sc, a1 = (acc[i][j][1] + by) * sc;
                const float a2 = (acc[i][j][2] + bx) * sc, a3 = (acc[i][j][3] + by) * sc;
                const int h = n >> 6, dd = n & 63;
                const int b0 = m0 >> 11, s0 = m0 & 2047;
                const int m1 = m0 + 8;
                const int b1 = m1 >> 11, s1 = m1 & 2047;
                const size_t i0 = (((size_t)(b0 * NH + h) * S_) + s0) * HD + dd;
                const size_t i1 = (((size_t)(b1 * NH + h) * S_) + s1) * HD + dd;
                __nv_bfloat16 h0, l0, h1, l1;
                splitf(a0, h0, l0); splitf(a1, h1, l1);
                *(uint32_t*)&oh[i0] = packraw(h0, h1);
                *(uint32_t*)&ol[i0] = packraw(l0, l1);
                splitf(a2, h0, l0); splitf(a3, h1, l1);
                *(uint32_t*)&oh[i1] = packraw(h0, h1);
                *(uint32_t*)&ol[i1] = packraw(l0, l1);
            } else {
                *(float2*)&outp[(size_t)m0 * ntot + n] =
                    make_float2(acc[i][j][0] + bx, acc[i][j][1] + by);
                *(float2*)&outp[(size_t)(m0 + 8) * ntot + n] =
                    make_float2(acc[i][j][2] + bx, acc[i][j][3] + by);
            }
        }
    }
}

// ============================ FA2-style attention on mma.sync ============================
// Block = one (b,h) x 128 q rows; 8 warps x 16 q rows. Inputs pre-split bf16 (Q pre-scaled).
#define VP 72                       // bf16 row stride (64 + 8 pad); 144B = 9*16B
#define TSZ (128*VP)                // 9216 bf16 per tile
#define ASMEM_BYTES (6*TSZ*2)       // 110592

__global__ __launch_bounds__(256, 1) void attn_mma()
{
    extern __shared__ __nv_bfloat16 sm[];
    __nv_bfloat16* sQh = sm;
    __nv_bfloat16* sQl = sm + TSZ;
    __nv_bfloat16* sKh = sm + 2*TSZ;
    __nv_bfloat16* sKl = sm + 3*TSZ;
    __nv_bfloat16* sVh = sm + 4*TSZ;
    __nv_bfloat16* sVl = sm + 5*TSZ;

    const int tid = threadIdx.x, wid = tid >> 5, lid = tid & 31;
    const int g = lid >> 2, tg = lid & 3;
    const int seg = lid >> 3, li = lid & 7;
    const int hb = blockIdx.y;
    const int b = hb >> 3, h = hb & 7;
    const int qs = blockIdx.x * 128;

    const size_t headOff = (size_t)(b * NH + h) * S_ * HD;
    const __nv_bfloat16* Qh = g_qh + headOff;
    const __nv_bfloat16* Ql = g_ql + headOff;
    const __nv_bfloat16* Kh = g_kh + headOff;
    const __nv_bfloat16* Kl = g_kl + headOff;
    const __nv_bfloat16* Vh = g_vh + headOff;
    const __nv_bfloat16* Vl = g_vl + headOff;

    // ---- load Q tile (pre-split, pre-scaled) ----
#pragma unroll
    for (int it = 0; it < 4; it++) {
        const int idx = it * 256 + tid;          // 1024 uint4 per array
        const int row = idx >> 3, c8 = idx & 7;
        const size_t so = (size_t)(qs + row) * HD + c8 * 8;
        *(uint4*)&sQh[row * VP + c8 * 8] = *(const uint4*)&Qh[so];
        *(uint4*)&sQl[row * VP + c8 * 8] = *(const uint4*)&Ql[so];
    }
    __syncthreads();

    // ---- preload Q A-frags for this warp's 16 rows ----
    const int m0 = wid * 16;
    uint32_t qh[4][4], ql[4][4];
#pragma unroll
    for (int ks = 0; ks < 4; ks++) {
        const int k0 = ks * 16 + tg * 2;
        qh[ks][0] = *(const uint32_t*)&sQh[(m0 + g) * VP + k0];
        qh[ks][1] = *(const uint32_t*)&sQh[(m0 + g + 8) * VP + k0];
        qh[ks][2] = *(const uint32_t*)&sQh[(m0 + g) * VP + k0 + 8];
        qh[ks][3] = *(const uint32_t*)&sQh[(m0 + g + 8) * VP + k0 + 8];
        ql[ks][0] = *(const uint32_t*)&sQl[(m0 + g) * VP + k0];
        ql[ks][1] = *(const uint32_t*)&sQl[(m0 + g + 8) * VP + k0];
        ql[ks][2] = *(const uint32_t*)&sQl[(m0 + g) * VP + k0 + 8];
        ql[ks][3] = *(const uint32_t*)&sQl[(m0 + g + 8) * VP + k0 + 8];
    }

    const uint32_t skh_base = smem_u32(sKh);
    const uint32_t skl_base = smem_u32(sKl);
    const uint32_t svh_base = smem_u32(sVh);
    const uint32_t svl_base = smem_u32(sVl);

    float mrow[2] = {-1e30f, -1e30f};
    float lrow[2] = {0.f, 0.f};
    float accO[8][4];
#pragma unroll
    for (int j = 0; j < 8; j++)
#pragma unroll
        for (int r = 0; r < 4; r++) accO[j][r] = 0.f;

    for (int kt = 0; kt < 16; kt++) {
        __syncthreads();   // protect previous iteration's K/V reads
        // ---- load K & V tiles (pre-split copies) ----
#pragma unroll
        for (int it = 0; it < 4; it++) {
            const int idx = it * 256 + tid;      // 1024 uint4 per array
            const int row = idx >> 3, c8 = idx & 7;
            const size_t so = (size_t)(kt * 128 + row) * HD + c8 * 8;
            const int dofs = row * VP + c8 * 8;
            *(uint4*)&sKh[dofs] = *(const uint4*)&Kh[so];
            *(uint4*)&sKl[dofs] = *(const uint4*)&Kl[so];
            *(uint4*)&sVh[dofs] = *(const uint4*)&Vh[so];
            *(uint4*)&sVl[dofs] = *(const uint4*)&Vl[so];
        }
        __syncthreads();

        // ---- S = Q K^T; K B-frags via ldmatrix.x4 (non-trans) ----
        float accS[16][4];
#pragma unroll
        for (int j = 0; j < 16; j++)
#pragma unroll
            for (int r = 0; r < 4; r++) accS[j][r] = 0.f;

#pragma unroll
        for (int jj = 0; jj < 16; jj++) {
            const int n0 = jj * 8;
            const uint32_t rowb = (uint32_t)((n0 + li) * VP) * 2 + seg * 16;
            uint32_t bh8[8], bl8[8];
            ldmx4n(&bh8[0], skh_base + rowb);         // k 0..31
            ldmx4n(&bh8[4], skh_base + rowb + 64);    // k 32..63
            ldmx4n(&bl8[0], skl_base + rowb);
            ldmx4n(&bl8[4], skl_base + rowb + 64);
#pragma unroll
            for (int ks = 0; ks < 4; ks++) {
                mma16816(accS[jj], qh[ks], &bh8[ks * 2]);
                mma16816(accS[jj], qh[ks], &bl8[ks * 2]);
                mma16816(accS[jj], ql[ks], &bh8[ks * 2]);
            }
        }

        // ---- online softmax (rows g and g+8 owned by quad lanes) ----
        float alpha[2];
#pragma unroll
        for (int r = 0; r < 2; r++) {
            float mt = -1e30f;
#pragma unroll
            for (int jj = 0; jj < 16; jj++)
                mt = fmaxf(mt, fmaxf(accS[jj][2*r], accS[jj][2*r+1]));
            mt = fmaxf(mt, __shfl_xor_sync(0xffffffffu, mt, 1));
            mt = fmaxf(mt, __shfl_xor_sync(0xffffffffu, mt, 2));
            const float mn = fmaxf(mrow[r], mt);
            alpha[r] = __expf(mrow[r] - mn);
            mrow[r] = mn;
        }
        float ls0 = 0.f, ls1 = 0.f;
#pragma unroll
        for (int jj = 0; jj < 16; jj++) {
            float p0 = __expf(accS[jj][0] - mrow[0]);
            float p1 = __expf(accS[jj][1] - mrow[0]);
            float p2 = __expf(accS[jj][2] - mrow[1]);
            float p3 = __expf(accS[jj][3] - mrow[1]);
            accS[jj][0] = p0; accS[jj][1] = p1; accS[jj][2] = p2; accS[jj][3] = p3;
            ls0 += p0 + p1; ls1 += p2 + p3;
        }
        ls0 += __shfl_xor_sync(0xffffffffu, ls0, 1);
        ls0 += __shfl_xor_sync(0xffffffffu, ls0, 2);
        ls1 += __shfl_xor_sync(0xffffffffu, ls1, 1);
        ls1 += __shfl_xor_sync(0xffffffffu, ls1, 2);
        lrow[0] = lrow[0] * alpha[0] + ls0;
        lrow[1] = lrow[1] * alpha[1] + ls1;
#pragma unroll
        for (int j = 0; j < 8; j++) {
            accO[j][0] *= alpha[0]; accO[j][1] *= alpha[0];
            accO[j][2] *= alpha[1]; accO[j][3] *= alpha[1];
        }

        // ---- O += P V (V B-frags via ldmatrix.trans, P split hi/lo) ----
        const int lr = lid & 7, sel = lid >> 3;
        const int rofs = ((sel & 1) ? 8 : 0) + lr;
        const int cofs = (sel & 2) ? 8 : 0;
#pragma unroll
        for (int kk = 0; kk < 8; kk++) {
            uint32_t pah[4], pal[4];
            {
                const float* s0 = accS[2*kk];
                const float* s1 = accS[2*kk + 1];
                __nv_bfloat16 h0, l0, h1, l1;
                splitf(s0[0], h0, l0); splitf(s0[1], h1, l1);
                pah[0] = packraw(h0, h1); pal[0] = packraw(l0, l1);
                splitf(s0[2], h0, l0); splitf(s0[3], h1, l1);
                pah[1] = packraw(h0, h1); pal[1] = packraw(l0, l1);
                splitf(s1[0], h0, l0); splitf(s1[1], h1, l1);
                pah[2] = packraw(h0, h1); pal[2] = packraw(l0, l1);
                splitf(s1[2], h0, l0); splitf(s1[3], h1, l1);
                pah[3] = packraw(h0, h1); pal[3] = packraw(l0, l1);
            }
            const int k0 = kk * 16;
#pragma unroll
            for (int dn = 0; dn < 4; dn++) {
                const int d0 = dn * 16;
                const uint32_t boff = (uint32_t)((k0 + rofs) * VP + d0 + cofs) * 2;
                uint32_t vh[4], vl[4];
                ldmx4t(vh, svh_base + boff);
                ldmx4t(vl, svl_base + boff);
                mma16816(accO[dn*2],     pah, &vh[0]);
                mma16816(accO[dn*2],     pah, &vl[0]);
                mma16816(accO[dn*2],     pal, &vh[0]);
                mma16816(accO[dn*2 + 1], pah, &vh[2]);
                mma16816(accO[dn*2 + 1], pah, &vl[2]);
                mma16816(accO[dn*2 + 1], pal, &vh[2]);
            }
        }
    }

    // ---- epilogue: normalize, split, write head-major bf16 pairs ----
    const float inv0 = 1.f / lrow[0];
    const float inv1 = 1.f / lrow[1];
    const int q0 = qs + m0 + g;
#pragma unroll
    for (int j = 0; j < 8; j++) {
        const int d = h * HD + j * 8 + tg * 2;
        const size_t i0 = ((size_t)(b * S_ + q0)) * HID + d;
        const size_t i1 = ((size_t)(b * S_ + q0 + 8)) * HID + d;
        __nv_bfloat16 h0, l0, h1, l1;
        splitf(accO[j][0] * inv0, h0, l0); splitf(accO[j][1] * inv0, h1, l1);
        *(uint32_t*)&g_ath[i0] = packraw(h0, h1);
        *(uint32_t*)&g_atl[i0] = packraw(l0, l1);
        splitf(accO[j][2] * inv1, h0, l0); splitf(accO[j][3] * inv1, h1, l1);
        *(uint32_t*)&g_ath[i1] = packraw(h0, h1);
        *(uint32_t*)&g_atl[i1] = packraw(l0, l1);
    }
}

// ---------------------------------------------------------------------------
extern "C" void kernel_launch(void* const* d_in, const int* in_sizes, int n_in,
                              void* d_out, int out_size)
{
    const float* X  = (const float*)d_in[0];
    const float* Wq = (const float*)d_in[1];
    const float* bq = (const float*)d_in[2];
    const float* Wk = (const float*)d_in[3];
    const float* bk = (const float*)d_in[4];
    const float* Wv = (const float*)d_in[5];
    const float* bv = (const float*)d_in[6];
    const float* Wo = (const float*)d_in[7];
    const float* bo = (const float*)d_in[8];
    float* out = (float*)d_out;

    cudaFuncSetAttribute(attn_mma, cudaFuncAttributeMaxDynamicSharedMemorySize,
                         ASMEM_BYTES);

    // 0) prep: split X; transpose+split weights
    prep_split<<<M_*TD/4/256, 256>>>(X);
    prep_transpose<<<dim3(TD/32, HID/32), 256>>>(Wq, TD, HID, 0 * TDHID);
    prep_transpose<<<dim3(TD/32, HID/32), 256>>>(Wk, TD, HID, 1 * TDHID);
    prep_transpose<<<dim3(TD/32, HID/32), 256>>>(Wv, TD, HID, 2 * TDHID);
    prep_transpose<<<dim3(HID/32, VD/32), 256>>>(Wo, HID, VD, 3 * TDHID);

    // 1) QKV projections (mma.sync split-bf16)
    mma_gemm<<<dim3(HID/128, M_/128), 256>>>(bq, nullptr, TD, HID, 0 * TDHID, 0);
    mma_gemm<<<dim3(HID/128, M_/128), 256>>>(bk, nullptr, TD, HID, 1 * TDHID, 1);
    mma_gemm<<<dim3(HID/128, M_/128), 256>>>(bv, nullptr, TD, HID, 2 * TDHID, 2);

    // 2) attention (FA2-style mma.sync)
    attn_mma<<<dim3(S_/128, B_*NH), 256, ASMEM_BYTES>>>();

    // 3) output projection
    mma_gemm<<<dim3(VD/128, M_/128), 256>>>(bo, out, HID, VD, 3 * TDHID, 3);
}

// round 15
// speedup vs baseline: 1.0321x; 1.0321x over previous
#include <cuda_runtime.h>
#include <cuda_bf16.h>
#include <cstdint>

#define B_  4
#define S_  2048
#define TD  768
#define HID 512
#define NH  8
#define HD  64
#define VD  768
#define M_  (B_*S_)   // 8192
#define TDHID (TD*HID)

// Scratch (allocation-free rule: __device__ globals) — all intermediates split bf16 hi/lo
__device__ __nv_bfloat16 g_xh[M_*TD],  g_xl[M_*TD];
__device__ __nv_bfloat16 g_qh[M_*HID], g_ql[M_*HID];
__device__ __nv_bfloat16 g_kh[M_*HID], g_kl[M_*HID];
__device__ __nv_bfloat16 g_vh[M_*HID], g_vl[M_*HID];
__device__ __nv_bfloat16 g_ath[M_*HID], g_atl[M_*HID];
// transposed + split weights: [0..3*TDHID) = Wq,Wk,Wv as [n][k]; [3*TDHID..) = Wo as [n][k]
__device__ __nv_bfloat16 g_bh[3*TDHID + VD*HID];
__device__ __nv_bfloat16 g_bl[3*TDHID + VD*HID];

struct alignas(8) bf4 { __nv_bfloat16 v[4]; };

__device__ __forceinline__ uint32_t smem_u32(const void* p) {
    uint32_t a;
    asm("{ .reg .u64 t; cvta.to.shared.u64 t, %1; cvt.u32.u64 %0, t; }" : "=r"(a) : "l"(p));
    return a;
}
__device__ __forceinline__ void splitf(float x, __nv_bfloat16& h, __nv_bfloat16& l) {
    h = __float2bfloat16(x);
    l = __float2bfloat16(x - __bfloat162float(h));
}
__device__ __forceinline__ uint32_t packraw(__nv_bfloat16 a, __nv_bfloat16 b) {
    return ((uint32_t)*(uint16_t*)&b << 16) | *(uint16_t*)&a;
}

// ============================ input prep: split X once ============================
__global__ __launch_bounds__(256) void prep_split(const float* __restrict__ X)
{
    const int idx = blockIdx.x * 256 + threadIdx.x;   // over float4
    float4 a = *(const float4*)&X[(size_t)idx * 4];
    bf4 h, l;
    splitf(a.x, h.v[0], l.v[0]); splitf(a.y, h.v[1], l.v[1]);
    splitf(a.z, h.v[2], l.v[2]); splitf(a.w, h.v[3], l.v[3]);
    *(bf4*)&g_xh[(size_t)idx * 4] = h;
    *(bf4*)&g_xl[(size_t)idx * 4] = l;
}

// ============================ weight prep: transpose + bf16 split ============================
__global__ __launch_bounds__(256) void prep_transpose(const float* __restrict__ W,
                                                      int rows, int cols, int dst_off)
{
    __shared__ float t[32][33];
    const int tx = threadIdx.x & 31, ty = threadIdx.x >> 5;
    const int k0 = blockIdx.x * 32, n0 = blockIdx.y * 32;
#pragma unroll
    for (int j = 0; j < 4; j++) {
        const int k = k0 + ty + j * 8;
        t[ty + j * 8][tx] = W[(size_t)k * cols + n0 + tx];
    }
    __syncthreads();
#pragma unroll
    for (int j = 0; j < 4; j++) {
        const int n = n0 + ty + j * 8;
        const int k = k0 + tx;
        const float x = t[tx][ty + j * 8];
        __nv_bfloat16 h, l; splitf(x, h, l);
        g_bh[dst_off + (size_t)n * rows + k] = h;
        g_bl[dst_off + (size_t)n * rows + k] = l;
    }
}

// ============================ mma.sync helpers ============================
__device__ __forceinline__ void mma16816(float* d, const uint32_t* a, const uint32_t* b)
{
    asm volatile(
        "mma.sync.aligned.m16n8k16.row.col.f32.bf16.bf16.f32 "
        "{%0,%1,%2,%3}, {%4,%5,%6,%7}, {%8,%9}, {%0,%1,%2,%3};"
        : "+f"(d[0]), "+f"(d[1]), "+f"(d[2]), "+f"(d[3])
        : "r"(a[0]), "r"(a[1]), "r"(a[2]), "r"(a[3]), "r"(b[0]), "r"(b[1]));
}
__device__ __forceinline__ void ldmx4t(uint32_t* r, uint32_t addr)
{
    asm volatile("ldmatrix.sync.aligned.m8n8.x4.trans.shared.b16 {%0,%1,%2,%3}, [%4];"
                 : "=r"(r[0]), "=r"(r[1]), "=r"(r[2]), "=r"(r[3]) : "r"(addr));
}

// ============================ mma.sync split-bf16 GEMM (projections) ============================
// A pre-split bf16: outsel<3 -> g_xh/g_xl; outsel 3 -> g_ath/g_atl.
// outsel 0/1/2: head-major split bf16 into g_{q,k,v}{h,l} (Q pre-scaled by 0.125)
// outsel 3: fp32 row-major into outp.
#define APAD 40

__global__ __launch_bounds__(256) void mma_gemm(
    const float* __restrict__ bias, float* __restrict__ outp,
    int ktot, int ntot, int boff, int outsel)
{
    __shared__ __nv_bfloat16 sAh[128 * APAD];
    __shared__ __nv_bfloat16 sAl[128 * APAD];
    __shared__ __nv_bfloat16 sBh[128 * APAD];
    __shared__ __nv_bfloat16 sBl[128 * APAD];

    const int tid = threadIdx.x;
    const int wid = tid >> 5, lid = tid & 31;
    const int wm = wid >> 1, wn = wid & 1;
    const int g = lid >> 2, tg = lid & 3;
    const int rowBase = blockIdx.y * 128;
    const int colBase = blockIdx.x * 128;
    const int nc = ktot / 32;

    const __nv_bfloat16* Ah = (outsel == 3) ? g_ath : g_xh;
    const __nv_bfloat16* Al = (outsel == 3) ? g_atl : g_xl;
    const __nv_bfloat16* Bh = g_bh + boff;
    const __nv_bfloat16* Bl = g_bl + boff;

    float acc[2][8][4];
#pragma unroll
    for (int i = 0; i < 2; i++)
#pragma unroll
        for (int j = 0; j < 8; j++)
#pragma unroll
            for (int r = 0; r < 4; r++) acc[i][j][r] = 0.f;

    for (int c = 0; c < nc; c++) {
        // ---- A chunk: 128 rows x 32 k, pre-split copies ----
        {
            const __nv_bfloat16* Ah_src = Ah + (size_t)rowBase * ktot + c * 32;
            const __nv_bfloat16* Al_src = Al + (size_t)rowBase * ktot + c * 32;
#pragma unroll
            for (int it = 0; it < 2; it++) {
                const int idx = it * 256 + tid;       // 512 uint4
                const int n = idx >> 2, c8 = idx & 3;
                const size_t so = (size_t)n * ktot + c8 * 8;
                *(uint4*)&sAh[n * APAD + c8 * 8] = *(const uint4*)&Ah_src[so];
                *(uint4*)&sAl[n * APAD + c8 * 8] = *(const uint4*)&Al_src[so];
            }
        }
        // ---- B chunk: 128 n-rows x 32 k ----
        {
#pragma unroll
            for (int it = 0; it < 2; it++) {
                const int idx = it * 256 + tid;
                const int n = idx >> 2, c8 = idx & 3;
                const size_t go = (size_t)(colBase + n) * ktot + c * 32 + c8 * 8;
                *(uint4*)&sBh[n * APAD + c8 * 8] = *(const uint4*)&Bh[go];
                *(uint4*)&sBl[n * APAD + c8 * 8] = *(const uint4*)&Bl[go];
            }
        }
        __syncthreads();

#pragma unroll
        for (int ks = 0; ks < 2; ks++) {
            const int k0 = ks * 16 + tg * 2;
            uint32_t ah[2][4], al[2][4];
#pragma unroll
            for (int i = 0; i < 2; i++) {
                const int r0 = wm * 32 + i * 16 + g;
                ah[i][0] = *(const uint32_t*)&sAh[r0 * APAD + k0];
                ah[i][1] = *(const uint32_t*)&sAh[(r0 + 8) * APAD + k0];
                ah[i][2] = *(const uint32_t*)&sAh[r0 * APAD + k0 + 8];
                ah[i][3] = *(const uint32_t*)&sAh[(r0 + 8) * APAD + k0 + 8];
                al[i][0] = *(const uint32_t*)&sAl[r0 * APAD + k0];
                al[i][1] = *(const uint32_t*)&sAl[(r0 + 8) * APAD + k0];
                al[i][2] = *(const uint32_t*)&sAl[r0 * APAD + k0 + 8];
                al[i][3] = *(const uint32_t*)&sAl[(r0 + 8) * APAD + k0 + 8];
            }
#pragma unroll
            for (int j = 0; j < 8; j++) {
                const int n0 = wn * 64 + j * 8 + g;
                uint32_t bh[2], bl[2];
                bh[0] = *(const uint32_t*)&sBh[n0 * APAD + k0];
                bh[1] = *(const uint32_t*)&sBh[n0 * APAD + k0 + 8];
                bl[0] = *(const uint32_t*)&sBl[n0 * APAD + k0];
                bl[1] = *(const uint32_t*)&sBl[n0 * APAD + k0 + 8];
#pragma unroll
                for (int i = 0; i < 2; i++) {
                    mma16816(acc[i][j], ah[i], bh);
                    mma16816(acc[i][j], ah[i], bl);
                    mma16816(acc[i][j], al[i], bh);
                }
            }
        }
        __syncthreads();
    }

    // ---- epilogue ----
    __nv_bfloat16* oh = (outsel == 0) ? g_qh : (outsel == 1) ? g_kh : g_vh;
    __nv_bfloat16* ol = (outsel == 0) ? g_ql : (outsel == 1) ? g_kl : g_vl;
    const float sc = (outsel == 0) ? 0.125f : 1.f;    // fold 1/sqrt(64) into Q
#pragma unroll
    for (int i = 0; i < 2; i++) {
        const int m0 = rowBase + wm * 32 + i * 16 + g;
#pragma unroll
        for (int j = 0; j < 8; j++) {
            const int n = colBase + wn * 64 + j * 8 + tg * 2;
            const float bx = __ldg(&bias[n]), by = __ldg(&bias[n + 1]);
            if (outsel < 3) {
                const float a0 = (acc[i][j][0] + bx) * sc, a1 = (acc[i][j][1] + by) * sc;
                const float a2 = (acc[i][j][2] + bx) * sc, a3 = (acc[i][j][3] + by) * sc;
                const int h = n >> 6, dd = n & 63;
                const int b0 = m0 >> 11, s0 = m0 & 2047;
                const int m1 = m0 + 8;
                const int b1 = m1 >> 11, s1 = m1 & 2047;
                const size_t i0 = (((size_t)(b0 * NH + h) * S_) + s0) * HD + dd;
                const size_t i1 = (((size_t)(b1 * NH + h) * S_) + s1) * HD + dd;
                __nv_bfloat16 h0, l0, h1, l1;
                splitf(a0, h0, l0); splitf(a1, h1, l1);
                *(uint32_t*)&oh[i0] = packraw(h0, h1);
                *(uint32_t*)&ol[i0] = packraw(l0, l1);
                splitf(a2, h0, l0); splitf(a3, h1, l1);
                *(uint32_t*)&oh[i1] = packraw(h0, h1);
                *(uint32_t*)&ol[i1] = packraw(l0, l1);
            } else {
                *(float2*)&outp[(size_t)m0 * ntot + n] =
                    make_float2(acc[i][j][0] + bx, acc[i][j][1] + by);
                *(float2*)&outp[(size_t)(m0 + 8) * ntot + n] =
                    make_float2(acc[i][j][2] + bx, acc[i][j][3] + by);
            }
        }
    }
}

// ============================ FA2-style attention on mma.sync ============================
// Block = one (b,h) x 128 q rows; 8 warps x 16 q rows. Inputs pre-split bf16 (Q pre-scaled).
// S-loop uses R11-style per-ks LDS.32 fragment reads (low register pressure).
#define VP 72                       // bf16 row stride (64 + 8 pad); 144B = 9*16B
#define TSZ (128*VP)                // 9216 bf16 per tile
#define ASMEM_BYTES (6*TSZ*2)       // 110592

__global__ __launch_bounds__(256, 1) void attn_mma()
{
    extern __shared__ __nv_bfloat16 sm[];
    __nv_bfloat16* sQh = sm;
    __nv_bfloat16* sQl = sm + TSZ;
    __nv_bfloat16* sKh = sm + 2*TSZ;
    __nv_bfloat16* sKl = sm + 3*TSZ;
    __nv_bfloat16* sVh = sm + 4*TSZ;
    __nv_bfloat16* sVl = sm + 5*TSZ;

    const int tid = threadIdx.x, wid = tid >> 5, lid = tid & 31;
    const int g = lid >> 2, tg = lid & 3;
    const int hb = blockIdx.y;
    const int b = hb >> 3, h = hb & 7;
    const int qs = blockIdx.x * 128;

    const size_t headOff = (size_t)(b * NH + h) * S_ * HD;
    const __nv_bfloat16* Qh = g_qh + headOff;
    const __nv_bfloat16* Ql = g_ql + headOff;
    const __nv_bfloat16* Kh = g_kh + headOff;
    const __nv_bfloat16* Kl = g_kl + headOff;
    const __nv_bfloat16* Vh = g_vh + headOff;
    const __nv_bfloat16* Vl = g_vl + headOff;

    // ---- load Q tile (pre-split, pre-scaled) ----
#pragma unroll
    for (int it = 0; it < 4; it++) {
        const int idx = it * 256 + tid;          // 1024 uint4 per array
        const int row = idx >> 3, c8 = idx & 7;
        const size_t so = (size_t)(qs + row) * HD + c8 * 8;
        *(uint4*)&sQh[row * VP + c8 * 8] = *(const uint4*)&Qh[so];
        *(uint4*)&sQl[row * VP + c8 * 8] = *(const uint4*)&Ql[so];
    }
    __syncthreads();

    // ---- preload Q A-frags for this warp's 16 rows ----
    const int m0 = wid * 16;
    uint32_t qh[4][4], ql[4][4];
#pragma unroll
    for (int ks = 0; ks < 4; ks++) {
        const int k0 = ks * 16 + tg * 2;
        qh[ks][0] = *(const uint32_t*)&sQh[(m0 + g) * VP + k0];
        qh[ks][1] = *(const uint32_t*)&sQh[(m0 + g + 8) * VP + k0];
        qh[ks][2] = *(const uint32_t*)&sQh[(m0 + g) * VP + k0 + 8];
        qh[ks][3] = *(const uint32_t*)&sQh[(m0 + g + 8) * VP + k0 + 8];
        ql[ks][0] = *(const uint32_t*)&sQl[(m0 + g) * VP + k0];
        ql[ks][1] = *(const uint32_t*)&sQl[(m0 + g + 8) * VP + k0];
        ql[ks][2] = *(const uint32_t*)&sQl[(m0 + g) * VP + k0 + 8];
        ql[ks][3] = *(const uint32_t*)&sQl[(m0 + g + 8) * VP + k0 + 8];
    }

    const uint32_t svh_base = smem_u32(sVh);
    const uint32_t svl_base = smem_u32(sVl);

    float mrow[2] = {-1e30f, -1e30f};
    float lrow[2] = {0.f, 0.f};
    float accO[8][4];
#pragma unroll
    for (int j = 0; j < 8; j++)
#pragma unroll
        for (int r = 0; r < 4; r++) accO[j][r] = 0.f;

    for (int kt = 0; kt < 16; kt++) {
        __syncthreads();   // protect previous iteration's K/V reads
        // ---- load K & V tiles (pre-split copies) ----
#pragma unroll
        for (int it = 0; it < 4; it++) {
            const int idx = it * 256 + tid;      // 1024 uint4 per array
            const int row = idx >> 3, c8 = idx & 7;
            const size_t so = (size_t)(kt * 128 + row) * HD + c8 * 8;
            const int dofs = row * VP + c8 * 8;
            *(uint4*)&sKh[dofs] = *(const uint4*)&Kh[so];
            *(uint4*)&sKl[dofs] = *(const uint4*)&Kl[so];
            *(uint4*)&sVh[dofs] = *(const uint4*)&Vh[so];
            *(uint4*)&sVl[dofs] = *(const uint4*)&Vl[so];
        }
        __syncthreads();

        // ---- S = Q K^T for this warp's 16 q rows x 128 keys (per-ks LDS.32 frags) ----
        float accS[16][4];
#pragma unroll
        for (int j = 0; j < 16; j++)
#pragma unroll
            for (int r = 0; r < 4; r++) accS[j][r] = 0.f;

#pragma unroll
        for (int jj = 0; jj < 16; jj++) {
            const int n0 = jj * 8 + g;
#pragma unroll
            for (int ks = 0; ks < 4; ks++) {
                const int k0 = ks * 16 + tg * 2;
                uint32_t bh[2], bl[2];
                bh[0] = *(const uint32_t*)&sKh[n0 * VP + k0];
                bh[1] = *(const uint32_t*)&sKh[n0 * VP + k0 + 8];
                bl[0] = *(const uint32_t*)&sKl[n0 * VP + k0];
                bl[1] = *(const uint32_t*)&sKl[n0 * VP + k0 + 8];
                mma16816(accS[jj], qh[ks], bh);
                mma16816(accS[jj], qh[ks], bl);
                mma16816(accS[jj], ql[ks], bh);
            }
        }

        // ---- online softmax (rows g and g+8 owned by quad lanes) ----
        float alpha[2];
#pragma unroll
        for (int r = 0; r < 2; r++) {
            float mt = -1e30f;
#pragma unroll
            for (int jj = 0; jj < 16; jj++)
                mt = fmaxf(mt, fmaxf(accS[jj][2*r], accS[jj][2*r+1]));
            mt = fmaxf(mt, __shfl_xor_sync(0xffffffffu, mt, 1));
            mt = fmaxf(mt, __shfl_xor_sync(0xffffffffu, mt, 2));
            const float mn = fmaxf(mrow[r], mt);
            alpha[r] = __expf(mrow[r] - mn);
            mrow[r] = mn;
        }
        float ls0 = 0.f, ls1 = 0.f;
#pragma unroll
        for (int jj = 0; jj < 16; jj++) {
            float p0 = __expf(accS[jj][0] - mrow[0]);
            float p1 = __expf(accS[jj][1] - mrow[0]);
            float p2 = __expf(accS[jj][2] - mrow[1]);
            float p3 = __expf(accS[jj][3] - mrow[1]);
            accS[jj][0] = p0; accS[jj][1] = p1; accS[jj][2] = p2; accS[jj][3] = p3;
            ls0 += p0 + p1; ls1 += p2 + p3;
        }
        ls0 += __shfl_xor_sync(0xffffffffu, ls0, 1);
        ls0 += __shfl_xor_sync(0xffffffffu, ls0, 2);
        ls1 += __shfl_xor_sync(0xffffffffu, ls1, 1);
        ls1 += __shfl_xor_sync(0xffffffffu, ls1, 2);
        lrow[0] = lrow[0] * alpha[0] + ls0;
        lrow[1] = lrow[1] * alpha[1] + ls1;
#pragma unroll
        for (int j = 0; j < 8; j++) {
            accO[j][0] *= alpha[0]; accO[j][1] *= alpha[0];
            accO[j][2] *= alpha[1]; accO[j][3] *= alpha[1];
        }

        // ---- O += P V (V B-frags via ldmatrix.trans, P split hi/lo) ----
        const int lr = lid & 7, sel = lid >> 3;
        const int rofs = ((sel & 1) ? 8 : 0) + lr;
        const int cofs = (sel & 2) ? 8 : 0;
#pragma unroll
        for (int kk = 0; kk < 8; kk++) {
            uint32_t pah[4], pal[4];
            {
                const float* s0 = accS[2*kk];
                const float* s1 = accS[2*kk + 1];
                __nv_bfloat16 h0, l0, h1, l1;
                splitf(s0[0], h0, l0); splitf(s0[1], h1, l1);
                pah[0] = packraw(h0, h1); pal[0] = packraw(l0, l1);
                splitf(s0[2], h0, l0); splitf(s0[3], h1, l1);
                pah[1] = packraw(h0, h1); pal[1] = packraw(l0, l1);
                splitf(s1[0], h0, l0); splitf(s1[1], h1, l1);
                pah[2] = packraw(h0, h1); pal[2] = packraw(l0, l1);
                splitf(s1[2], h0, l0); splitf(s1[3], h1, l1);
                pah[3] = packraw(h0, h1); pal[3] = packraw(l0, l1);
            }
            const int k0 = kk * 16;
#pragma unroll
            for (int dn = 0; dn < 4; dn++) {
                const int d0 = dn * 16;
                const uint32_t boff = (uint32_t)((k0 + rofs) * VP + d0 + cofs) * 2;
                uint32_t vh[4], vl[4];
                ldmx4t(vh, svh_base + boff);
                ldmx4t(vl, svl_base + boff);
                mma16816(accO[dn*2],     pah, &vh[0]);
                mma16816(accO[dn*2],     pah, &vl[0]);
                mma16816(accO[dn*2],     pal, &vh[0]);
                mma16816(accO[dn*2 + 1], pah, &vh[2]);
                mma16816(accO[dn*2 + 1], pah, &vl[2]);
                mma16816(accO[dn*2 + 1], pal, &vh[2]);
            }
        }
    }

    // ---- epilogue: normalize, split, write head-major bf16 pairs ----
    const float inv0 = 1.f / lrow[0];
    const float inv1 = 1.f / lrow[1];
    const int q0 = qs + m0 + g;
#pragma unroll
    for (int j = 0; j < 8; j++) {
        const int d = h * HD + j * 8 + tg * 2;
        const size_t i0 = ((size_t)(b * S_ + q0)) * HID + d;
        const size_t i1 = ((size_t)(b * S_ + q0 + 8)) * HID + d;
        __nv_bfloat16 h0, l0, h1, l1;
        splitf(accO[j][0] * inv0, h0, l0); splitf(accO[j][1] * inv0, h1, l1);
        *(uint32_t*)&g_ath[i0] = packraw(h0, h1);
        *(uint32_t*)&g_atl[i0] = packraw(l0, l1);
        splitf(accO[j][2] * inv1, h0, l0); splitf(accO[j][3] * inv1, h1, l1);
        *(uint32_t*)&g_ath[i1] = packraw(h0, h1);
        *(uint32_t*)&g_atl[i1] = packraw(l0, l1);
    }
}

// ---------------------------------------------------------------------------
extern "C" void kernel_launch(void* const* d_in, const int* in_sizes, int n_in,
                              void* d_out, int out_size)
{
    const float* X  = (const float*)d_in[0];
    const float* Wq = (const float*)d_in[1];
    const float* bq = (const float*)d_in[2];
    const float* Wk = (const float*)d_in[3];
    const float* bk = (const float*)d_in[4];
    const float* Wv = (const float*)d_in[5];
    const float* bv = (const float*)d_in[6];
    const float* Wo = (const float*)d_in[7];
    const float* bo = (const float*)d_in[8];
    float* out = (float*)d_out;

    cudaFuncSetAttribute(attn_mma, cudaFuncAttributeMaxDynamicSharedMemorySize,
                         ASMEM_BYTES);

    // 0) prep: split X; transpose+split weights
    prep_split<<<M_*TD/4/256, 256>>>(X);
    prep_transpose<<<dim3(TD/32, HID/32), 256>>>(Wq, TD, HID, 0 * TDHID);
    prep_transpose<<<dim3(TD/32, HID/32), 256>>>(Wk, TD, HID, 1 * TDHID);
    prep_transpose<<<dim3(TD/32, HID/32), 256>>>(Wv, TD, HID, 2 * TDHID);
    prep_transpose<<<dim3(HID/32, VD/32), 256>>>(Wo, HID, VD, 3 * TDHID);

    // 1) QKV projections (mma.sync split-bf16)
    mma_gemm<<<dim3(HID/128, M_/128), 256>>>(bq, nullptr, TD, HID, 0 * TDHID, 0);
    mma_gemm<<<dim3(HID/128, M_/128), 256>>>(bk, nullptr, TD, HID, 1 * TDHID, 1);
    mma_gemm<<<dim3(HID/128, M_/128), 256>>>(bv, nullptr, TD, HID, 2 * TDHID, 2);

    // 2) attention (FA2-style mma.sync)
    attn_mma<<<dim3(S_/128, B_*NH), 256, ASMEM_BYTES>>>();

    // 3) output projection
    mma_gemm<<<dim3(VD/128, M_/128), 256>>>(bo, out, HID, VD, 3 * TDHID, 3);
}